// round 9
// baseline (speedup 1.0000x reference)
#include <cuda_runtime.h>
#include <cuda_bf16.h>

// Problem: MultinomialCELoss
//   x: [N=8, Q=441, H=128, W=128] f32, y: [N=8, 2, H=128, W=128] f32
//   out[w] = -sum_{n,h} log( x[n, idx(n,h,w), h, w] )
//
// R9: R8 profiling isolated the single-CTA reduce as the bottleneck (4.3us on
// one SM, pure exposed L2 latency). Fix: spread the reduction over 128 CTAs
// (one per output element), each thread summing 8 independent partials then a
// shuffle+smem block tree. Gather kernel reverts to the measured-1.9us R3
// shape (1024 CTAs, one row/thread, coalesced store, no sync anywhere).

#define N_  8
#define Q_  441
#define H_  128
#define W_  128
#define HW_ (H_ * W_)
#define NBINS 21
#define ROWS_ (N_ * H_)              // 1024 flattened (n,h) rows

__device__ float g_partial[ROWS_ * W_];   // 512 KB, fully overwritten each run

__device__ __forceinline__ int ab_bin(float v) {
    // Match JAX f32 semantics: floor((v + 110) / 10), clipped to [0,20].
    // __fdiv_rn keeps IEEE division even under fast-math (bin boundaries).
    float q = floorf(__fdiv_rn(v + 110.0f, 10.0f));
    int qi = (int)q;
    qi = qi < 0 ? 0 : qi;
    qi = qi > (NBINS - 1) ? (NBINS - 1) : qi;
    return qi;
}

// Kernel A: CTA r handles flattened row r = n*128 + h. Thread w: 2 coalesced
// y loads -> 1 scattered x gather -> MUFU log -> coalesced store. 1024 CTAs
// keep ~28 warps/SM of gather parallelism (measured ~1.9us in R3).
__global__ __launch_bounds__(W_) void mce_gather_kernel(
    const float* __restrict__ x,
    const float* __restrict__ y,
    float* __restrict__ partial)
{
    const int w = threadIdx.x;        // 0..127
    const int r = blockIdx.x;         // 0..1023
    const int n = r >> 7;
    const int h = r & (H_ - 1);
    const int hw = h * W_ + w;

    float ya = y[(size_t)(n * 2 + 0) * HW_ + hw];
    float yb = y[(size_t)(n * 2 + 1) * HW_ + hw];
    const int idx = ab_bin(ya) * NBINS + ab_bin(yb);

    float v = x[((size_t)n * Q_ + idx) * HW_ + hw];

    partial[r * W_ + w] = __logf(v);
}

// Kernel B: CTA w reduces column w of partial[1024][128].
// Thread t sums rows t, t+128, ..., t+896 (8 independent loads, MLP=8),
// then shuffle+smem tree 128->1; lane 0 writes out[w] = -sum.
__global__ __launch_bounds__(128) void mce_reduce_kernel(
    const float* __restrict__ partial,
    float* __restrict__ out)
{
    const int w = blockIdx.x;         // 0..127
    const int t = threadIdx.x;        // 0..127

    float a0 = 0.f, a1 = 0.f, a2 = 0.f, a3 = 0.f;
    a0 = partial[(t          ) * W_ + w] + partial[(t + 128 * 4) * W_ + w];
    a1 = partial[(t + 128 * 1) * W_ + w] + partial[(t + 128 * 5) * W_ + w];
    a2 = partial[(t + 128 * 2) * W_ + w] + partial[(t + 128 * 6) * W_ + w];
    a3 = partial[(t + 128 * 3) * W_ + w] + partial[(t + 128 * 7) * W_ + w];
    float s = (a0 + a1) + (a2 + a3);

    // warp tree
    #pragma unroll
    for (int off = 16; off > 0; off >>= 1)
        s += __shfl_down_sync(0xffffffffu, s, off);

    __shared__ float red[4];
    if ((t & 31) == 0) red[t >> 5] = s;
    __syncthreads();

    if (t == 0) {
        out[w] = -(red[0] + red[1] + red[2] + red[3]);
    }
}

extern "C" void kernel_launch(void* const* d_in, const int* in_sizes, int n_in,
                              void* d_out, int out_size) {
    const float* x = (const float*)d_in[0];
    const float* y = (const float*)d_in[1];
    float* out = (float*)d_out;

    float* partial = nullptr;
    cudaGetSymbolAddress((void**)&partial, g_partial);

    mce_gather_kernel<<<ROWS_, W_>>>(x, y, partial);
    mce_reduce_kernel<<<W_, 128>>>(partial, out);
}

// round 10
// speedup vs baseline: 1.0323x; 1.0323x over previous
#include <cuda_runtime.h>
#include <cuda_bf16.h>

// Problem: MultinomialCELoss
//   x: [N=8, Q=441, H=128, W=128] f32, y: [N=8, 2, H=128, W=128] f32
//   out[w] = -sum_{n,h} log( x[n, idx(n,h,w), h, w] )
//
// R10: fused single kernel with a FENCE-FREE completion tail. R5/R7's fused
// versions were slow because every thread ran membar.gl (__threadfence) —
// an MIO storm. Instead: per-thread atomicAdd WITH return value (ATOMG's
// return arrives only after L2 applied the update); consuming the return
// creates a data dependency, so after __syncthreads() the CTA's counter
// bump provably follows all its accumulator updates. No membar anywhere.
// Gather: R1's proven shape — 128 CTAs x 128 thr, 8 batched gathers/thread.

#define N_  8
#define Q_  441
#define H_  128
#define W_  128
#define HW_ (H_ * W_)
#define NBINS 21
#define PAD 64                  // 256B stride: spread accs across L2 slices
#define GRID H_                 // 128 CTAs
#define TPB  W_                 // 128 threads

__device__ float g_acc[W_ * PAD];    // zero-initialized at module load
__device__ unsigned int g_count;     // zero-initialized at module load

__device__ __forceinline__ int ab_bin(float v) {
    // Match JAX f32 semantics: floor((v + 110) / 10), clipped to [0,20].
    // __fdiv_rn keeps IEEE division even under fast-math (bin boundaries).
    float q = floorf(__fdiv_rn(v + 110.0f, 10.0f));
    int qi = (int)q;
    qi = qi < 0 ? 0 : qi;
    qi = qi > (NBINS - 1) ? (NBINS - 1) : qi;
    return qi;
}

__global__ __launch_bounds__(TPB) void mce_fused_kernel(
    const float* __restrict__ x,
    const float* __restrict__ y,
    float* __restrict__ out)
{
    const int w = threadIdx.x;   // 0..127
    const int h = blockIdx.x;    // 0..127
    const int hw = h * W_ + w;

    // Stage all index math, then fire all 8 scattered gathers back-to-back.
    int idx[N_];
    #pragma unroll
    for (int n = 0; n < N_; n++) {
        float ya = y[(size_t)(n * 2 + 0) * HW_ + hw];
        float yb = y[(size_t)(n * 2 + 1) * HW_ + hw];
        idx[n] = ab_bin(ya) * NBINS + ab_bin(yb);
    }

    float v[N_];
    #pragma unroll
    for (int n = 0; n < N_; n++) {
        v[n] = x[((size_t)n * Q_ + idx[n]) * HW_ + hw];
    }

    float acc = 0.0f;
    #pragma unroll
    for (int n = 0; n < N_; n++) acc += __logf(v[n]);

    // Atomic WITH return: completion of this thread's update is known once
    // 'old' is consumed (ATOMG result write-back implies L2 application).
    float old = atomicAdd(&g_acc[w * PAD], acc);

    __shared__ unsigned int s_last;
    __shared__ int s_dummy;
    // Consume the return value (condition can never be true for finite log
    // sums, but the compiler cannot prove that, so the dependency is kept).
    if (__float_as_uint(old) == 0x7f800001u) s_dummy = 1;
    __syncthreads();   // all 128 returns consumed before the counter bump

    if (w == 0) {
        s_last = (atomicAdd(&g_count, 1u) == GRID - 1) ? 1u : 0u;
    }
    __syncthreads();

    if (s_last) {
        // Every other CTA bumped the counter only after its atomics were
        // applied at L2, so a .cg read here sees the final sums.
        float s = __ldcg(&g_acc[w * PAD]);
        out[w] = -s;
        g_acc[w * PAD] = 0.0f;            // restore zero state for replay
        if (w == 0) g_count = 0u;
    }
}

extern "C" void kernel_launch(void* const* d_in, const int* in_sizes, int n_in,
                              void* d_out, int out_size) {
    const float* x = (const float*)d_in[0];
    const float* y = (const float*)d_in[1];
    float* out = (float*)d_out;

    mce_fused_kernel<<<GRID, TPB>>>(x, y, out);
}

// round 11
// speedup vs baseline: 1.3846x; 1.3413x over previous
#include <cuda_runtime.h>
#include <cuda_bf16.h>

// Problem: MultinomialCELoss
//   x: [N=8, Q=441, H=128, W=128] f32, y: [N=8, 2, H=128, W=128] f32
//   out[w] = -sum_{n,h} log( x[n, idx(n,h,w), h, w] )
//
// R11: ZERO inter-CTA communication. out has exactly 128 elements, so:
// one CTA per output element. CTA w sums its entire column (1024 rows) with
// 512 threads x 2 rows, then an intra-block shuffle+smem tree writes out[w].
// One node, no atomics, no fences, no scratch, no replay-state reset.
// y reads are 512B-strided (uncoalesced) but every 32B sector is shared by
// 8 CTAs through L2 -> DRAM y traffic stays 512KB; LTS ~8.4MB (~1.3K cyc).

#define N_  8
#define Q_  441
#define H_  128
#define W_  128
#define HW_ (H_ * W_)
#define NBINS 21
#define TPB 512
#define ROWS_PER_THREAD 2     // 1024 rows / 512 threads

__device__ __forceinline__ int ab_bin(float v) {
    // Match JAX f32 semantics: floor((v + 110) / 10), clipped to [0,20].
    // __fdiv_rn keeps IEEE division even under fast-math (bin boundaries).
    float q = floorf(__fdiv_rn(v + 110.0f, 10.0f));
    int qi = (int)q;
    qi = qi < 0 ? 0 : qi;
    qi = qi > (NBINS - 1) ? (NBINS - 1) : qi;
    return qi;
}

__global__ __launch_bounds__(TPB) void mce_column_kernel(
    const float* __restrict__ x,
    const float* __restrict__ y,
    float* __restrict__ out)
{
    const int w = blockIdx.x;     // 0..127: this CTA owns out[w]
    const int t = threadIdx.x;    // 0..511

    // Thread t handles flattened rows t and t+512.
    int idx[ROWS_PER_THREAD], n_[ROWS_PER_THREAD], hw_[ROWS_PER_THREAD];
    #pragma unroll
    for (int k = 0; k < ROWS_PER_THREAD; k++) {
        const int row = t + k * TPB;         // 0..1023
        const int n = row >> 7;
        const int h = row & (H_ - 1);
        n_[k] = n;
        hw_[k] = h * W_ + w;
        float ya = y[(size_t)(n * 2 + 0) * HW_ + hw_[k]];
        float yb = y[(size_t)(n * 2 + 1) * HW_ + hw_[k]];
        idx[k] = ab_bin(ya) * NBINS + ab_bin(yb);
    }

    float v[ROWS_PER_THREAD];
    #pragma unroll
    for (int k = 0; k < ROWS_PER_THREAD; k++) {
        v[k] = x[((size_t)n_[k] * Q_ + idx[k]) * HW_ + hw_[k]];
    }

    float s = 0.0f;
    #pragma unroll
    for (int k = 0; k < ROWS_PER_THREAD; k++) s += __logf(v[k]);

    // Intra-block tree: warp shuffle, then 16 warp sums through smem.
    #pragma unroll
    for (int off = 16; off > 0; off >>= 1)
        s += __shfl_down_sync(0xffffffffu, s, off);

    __shared__ float red[TPB / 32];          // 16 warp partials
    if ((t & 31) == 0) red[t >> 5] = s;
    __syncthreads();

    if (t < 32) {
        float r = (t < TPB / 32) ? red[t] : 0.0f;
        #pragma unroll
        for (int off = 8; off > 0; off >>= 1)
            r += __shfl_down_sync(0xffffffffu, r, off);
        if (t == 0) out[w] = -r;
    }
}

extern "C" void kernel_launch(void* const* d_in, const int* in_sizes, int n_in,
                              void* d_out, int out_size) {
    const float* x = (const float*)d_in[0];
    const float* y = (const float*)d_in[1];
    float* out = (float*)d_out;

    mce_column_kernel<<<W_, TPB>>>(x, y, out);
}